// round 5
// baseline (speedup 1.0000x reference)
#include <cuda_runtime.h>
#include <cuda_bf16.h>
#include <math.h>
#include <stdint.h>

// ---------------- problem constants ----------------
#define BB   8
#define TT   2048
#define CC   512
#define HH   16
#define HSZ  32
#define BT   (BB*TT)            // 16384
#define BTC  8388608            // BT*CC

typedef __nv_bfloat16 bf16;

// ---------------- scratch (static device memory; no allocs) ----------------
__device__ float g_xx [BTC];
__device__ float g_mixpre[BT*160];
__device__ float g_r  [BTC];
__device__ float g_k  [BTC];
__device__ float g_v  [BTC];
__device__ float g_g  [BTC];
__device__ float g_dec[BTC];
__device__ float g_y  [BTC];             // layout (b,h,t,i)

// split bf16 operand buffers
__device__ bf16 g_xxx_h[BTC]; __device__ bf16 g_xxx_l[BTC];
__device__ bf16 g_xw_h[BTC];  __device__ bf16 g_xw_l[BTC];
__device__ bf16 g_xk_h[BTC];  __device__ bf16 g_xk_l[BTC];
__device__ bf16 g_xv_h[BTC];  __device__ bf16 g_xv_l[BTC];
__device__ bf16 g_xr_h[BTC];  __device__ bf16 g_xr_l[BTC];
__device__ bf16 g_xg_h[BTC];  __device__ bf16 g_xg_l[BTC];
__device__ bf16 g_yg_h[BTC];  __device__ bf16 g_yg_l[BTC];
__device__ bf16 g_wt_h[BT*64]; __device__ bf16 g_wt_l[BT*64];
__device__ bf16 g_w_h [5*CC*CC];   // Wr,Wk,Wv,Wg,Wo split (N,K)
__device__ bf16 g_w_l [5*CC*CC];
__device__ bf16 g_w1t_h[160*CC];   // w1^T  (160,512)
__device__ bf16 g_w1t_l[160*CC];
__device__ bf16 g_td1t_h[64*CC];   // tdw1^T (64,512)
__device__ bf16 g_td1t_l[64*CC];
__device__ bf16 g_td2t_h[CC*64];   // tdw2^T (512,64)
__device__ bf16 g_td2t_l[CC*64];

// ---------------- helpers ----------------
__device__ __forceinline__ uint32_t smem_u32(const void* p) {
    uint32_t a;
    asm("{ .reg .u64 t; cvta.to.shared.u64 t, %1; cvt.u32.u64 %0, t; }" : "=r"(a) : "l"(p));
    return a;
}
__device__ __forceinline__ void ldsm4(uint32_t* r, uint32_t addr) {
    asm volatile("ldmatrix.sync.aligned.m8n8.x4.shared.b16 {%0,%1,%2,%3}, [%4];"
                 : "=r"(r[0]), "=r"(r[1]), "=r"(r[2]), "=r"(r[3]) : "r"(addr));
}
__device__ __forceinline__ void mma16816(float* c, const uint32_t* a, const uint32_t* b) {
    asm volatile("mma.sync.aligned.m16n8k16.row.col.f32.bf16.bf16.f32 "
                 "{%0,%1,%2,%3}, {%4,%5,%6,%7}, {%8,%9}, {%0,%1,%2,%3};"
                 : "+f"(c[0]), "+f"(c[1]), "+f"(c[2]), "+f"(c[3])
                 : "r"(a[0]), "r"(a[1]), "r"(a[2]), "r"(a[3]),
                   "r"(b[0]), "r"(b[1]));
}
__device__ __forceinline__ void cp16(uint32_t dst, const void* src, uint32_t sz) {
    asm volatile("cp.async.cg.shared.global [%0], [%1], 16, %2;"
                 :: "r"(dst), "l"(src), "r"(sz) : "memory");
}
#define CP_COMMIT() asm volatile("cp.async.commit_group;" ::: "memory")
#define CP_WAIT1()  asm volatile("cp.async.wait_group 1;" ::: "memory")
#define CP_WAIT0()  asm volatile("cp.async.wait_group 0;" ::: "memory")

__device__ __forceinline__ void split2(float f0, float f1, uint32_t& hi, uint32_t& lo) {
    __nv_bfloat162 h = __floats2bfloat162_rn(f0, f1);
    float r0 = f0 - __bfloat162float(h.x);
    float r1 = f1 - __bfloat162float(h.y);
    __nv_bfloat162 l = __floats2bfloat162_rn(r0, r1);
    hi = *(uint32_t*)&h;
    lo = *(uint32_t*)&l;
}

// ---------------- epilogues ----------------
enum { EPI_NONE=0, EPI_TANH=1, EPI_SILU=2, EPI_DECAY=4 };

template<int EPI>
__device__ __forceinline__ float apply_epi(float v, int col,
                                           const float* __restrict__ vecn)
{
    if constexpr (EPI == EPI_TANH)  { return tanhf(v); }
    if constexpr (EPI == EPI_SILU)  { return v / (1.f + expf(-v)); }
    if constexpr (EPI == EPI_DECAY) { return expf(-expf(vecn[col] + v)); }
    return v;
}

// ================= pgemm: split-bf16 GEMM, cp.async 3-stage pipeline =================
// C[m,n] = epi( sum_k (Ah+Al)[m,k] * (Bh+Bl)[n,k] ), 3 MMA passes.
// A: (BT,K) bf16 pair, B: (N,K) bf16 pair (row stride K). CTA tile 128x128x32.
// OSPLIT: write split-bf16 (Ch/Cl) instead of fp32 C.
#define PPAD 40
#define PMAT (128*PPAD*2)          // 10240 B
#define PSTG (4*PMAT)              // 40960 B : Ah,Al,Bh,Bl
#define PSMEM (3*PSTG)             // 122880 B

template<int EPI, bool OSPLIT>
__global__ void __launch_bounds__(256)
pgemm(const bf16* __restrict__ Ah, const bf16* __restrict__ Al,
      const bf16* __restrict__ Bh, const bf16* __restrict__ Bl,
      float* __restrict__ C, bf16* __restrict__ Ch, bf16* __restrict__ Cl,
      int ldc, int N, int K,
      const float* __restrict__ vecn)
{
    extern __shared__ __align__(16) char sm[];
    const int tid  = threadIdx.x;
    const int warp = tid >> 5;
    const int lane = tid & 31;
    const int m0 = blockIdx.y * 128;
    const int n0 = blockIdx.x * 128;
    const int wm = (warp >> 2) * 64;
    const int wn = (warp & 3) * 32;
    const uint32_t sbase = smem_u32(sm);
    const int nch = K >> 5;

    auto issue = [&](int ci) {
        const uint32_t st = sbase + (uint32_t)(ci % 3) * PSTG;
        const int k0 = ci << 5;
        #pragma unroll
        for (int q = 0; q < 8; ++q) {
            const int cid  = q * 256 + tid;
            const int c    = cid & 3;
            const int r    = (cid >> 2) & 127;
            const int mat  = (cid >> 9) & 1;      // 0=hi 1=lo
            const int ab   = cid >> 10;           // 0=A 1=B
            const uint32_t dst = st + (uint32_t)ab * (2*PMAT) + (uint32_t)mat * PMAT
                               + (uint32_t)r * 80 + (uint32_t)c * 16;
            uint32_t sz = 16;
            int row;
            if (ab) {
                row = n0 + r;
                if (row >= N) { sz = 0; row = 0; }
            } else {
                row = m0 + r;
            }
            const bf16* srcb = ab ? (mat ? Bl : Bh) : (mat ? Al : Ah);
            const bf16* src  = srcb + (size_t)row * K + k0 + c * 8;
            cp16(dst, src, sz);
        }
        CP_COMMIT();
    };

    float acc[4][4][4];
    #pragma unroll
    for (int i = 0; i < 4; ++i)
        #pragma unroll
        for (int j = 0; j < 4; ++j)
            #pragma unroll
            for (int q = 0; q < 4; ++q) acc[i][j][q] = 0.f;

    const int a_r  = wm + (lane & 15);
    const int a_c8 = (lane >> 4) << 3;
    const int b_r  = wn + (lane & 7) + ((lane >> 4) << 3);
    const int b_c8 = ((lane >> 3) & 1) << 3;

    issue(0);
    if (nch > 1) issue(1);

    for (int ci = 0; ci < nch; ++ci) {
        if (ci < nch - 1) { CP_WAIT1(); } else { CP_WAIT0(); }
        __syncthreads();
        if (ci + 2 < nch) issue(ci + 2);

        const uint32_t st = sbase + (uint32_t)(ci % 3) * PSTG;
        const uint32_t uA_h = st;
        const uint32_t uA_l = st + PMAT;
        const uint32_t uB_h = st + 2*PMAT;
        const uint32_t uB_l = st + 3*PMAT;

        #pragma unroll
        for (int ks = 0; ks < 2; ++ks) {
            const int k0 = ks * 16;
            uint32_t ah[4][4], al[4][4], bh[2][4], bl[2][4];
            #pragma unroll
            for (int mt = 0; mt < 4; ++mt) {
                uint32_t off = (uint32_t)((a_r + mt*16) * PPAD + k0 + a_c8) * 2;
                ldsm4(ah[mt], uA_h + off);
                ldsm4(al[mt], uA_l + off);
            }
            #pragma unroll
            for (int bp = 0; bp < 2; ++bp) {
                uint32_t off = (uint32_t)((b_r + bp*16) * PPAD + k0 + b_c8) * 2;
                ldsm4(bh[bp], uB_h + off);
                ldsm4(bl[bp], uB_l + off);
            }
            #pragma unroll
            for (int mt = 0; mt < 4; ++mt)
                #pragma unroll
                for (int nt = 0; nt < 4; ++nt) {
                    const uint32_t* fbh = &bh[nt >> 1][(nt & 1) * 2];
                    const uint32_t* fbl = &bl[nt >> 1][(nt & 1) * 2];
                    mma16816(acc[mt][nt], ah[mt], fbh);
                    mma16816(acc[mt][nt], al[mt], fbh);
                    mma16816(acc[mt][nt], ah[mt], fbl);
                }
        }
    }

    // epilogue
    #pragma unroll
    for (int mt = 0; mt < 4; ++mt) {
        const int r0 = m0 + wm + mt*16 + (lane >> 2);
        #pragma unroll
        for (int half = 0; half < 2; ++half) {
            const int row = r0 + half * 8;
            const size_t rb = (size_t)row * ldc;
            #pragma unroll
            for (int nt = 0; nt < 4; ++nt) {
                const int col = n0 + wn + nt*8 + (lane & 3)*2;
                if (col < N) {
                    float v0 = apply_epi<EPI>(acc[mt][nt][half*2+0], col,   vecn);
                    float v1 = apply_epi<EPI>(acc[mt][nt][half*2+1], col+1, vecn);
                    if constexpr (OSPLIT) {
                        uint32_t hh, ll;
                        split2(v0, v1, hh, ll);
                        *(uint32_t*)&Ch[rb + col] = hh;
                        *(uint32_t*)&Cl[rb + col] = ll;
                    } else {
                        *(float2*)&C[rb + col] = make_float2(v0, v1);
                    }
                }
            }
        }
    }
}

// ---------------- weight split kernels ----------------
__global__ void split_w(const float* __restrict__ W, bf16* __restrict__ h,
                        bf16* __restrict__ l, int n)
{
    int i = blockIdx.x * blockDim.x + threadIdx.x;
    if (i >= n) return;
    float v = W[i];
    bf16 hv = __float2bfloat16(v);
    h[i] = hv;
    l[i] = __float2bfloat16(v - __bfloat162float(hv));
}
// src is (K,N) row-major; out (N,K): out[n*K+k] = src[k*N+n]
__global__ void split_trans(const float* __restrict__ src, bf16* __restrict__ h,
                            bf16* __restrict__ l, int N, int K)
{
    int i = blockIdx.x * blockDim.x + threadIdx.x;
    if (i >= N * K) return;
    int n = i / K, k = i % K;
    float v = src[(size_t)k * N + n];
    bf16 hv = __float2bfloat16(v);
    h[i] = hv;
    l[i] = __float2bfloat16(v - __bfloat162float(hv));
}

// ---------------- prep: xx = shift(x)-x ; xxx split bf16 ----------------
__global__ void prep_kernel(const float* __restrict__ x,
                            const float* __restrict__ tmx,
                            float* __restrict__ xx,
                            bf16* __restrict__ xxx_h,
                            bf16* __restrict__ xxx_l)
{
    int i4 = blockIdx.x * blockDim.x + threadIdx.x;
    if (i4 >= BTC/4) return;
    size_t idx = (size_t)i4 * 4;
    int m = (int)(idx / CC);
    int c = (int)(idx % CC);
    int t = m % TT;
    float4 xv = *(const float4*)(x + idx);
    float4 xs;
    if (t == 0) { xs.x = xs.y = xs.z = xs.w = 0.f; }
    else        { xs = *(const float4*)(x + idx - CC); }
    float4 tm = *(const float4*)(tmx + c);
    float4 d, e;
    d.x = xs.x - xv.x; d.y = xs.y - xv.y; d.z = xs.z - xv.z; d.w = xs.w - xv.w;
    e.x = fmaf(d.x, tm.x, xv.x); e.y = fmaf(d.y, tm.y, xv.y);
    e.z = fmaf(d.z, tm.z, xv.z); e.w = fmaf(d.w, tm.w, xv.w);
    *(float4*)(xx + idx) = d;
    uint32_t h0, h1, l0, l1;
    split2(e.x, e.y, h0, l0);
    split2(e.z, e.w, h1, l1);
    *(uint2*)(xxx_h + idx) = make_uint2(h0, h1);
    *(uint2*)(xxx_l + idx) = make_uint2(l0, l1);
}

// ---------------- mix5: fused 5-stream token-mix, all outputs split bf16 ----------------
__global__ void __launch_bounds__(256)
mix5_kernel(const float* __restrict__ mixpre,   // (BT,160)
            const float* __restrict__ w2,       // (5,32,512)
            const float* __restrict__ x,
            const float* __restrict__ xx,
            const float* __restrict__ tmw, const float* __restrict__ tmk,
            const float* __restrict__ tmv, const float* __restrict__ tmr,
            const float* __restrict__ tmg,
            bf16* __restrict__ xw_h, bf16* __restrict__ xw_l,
            bf16* __restrict__ xk_h, bf16* __restrict__ xk_l,
            bf16* __restrict__ xv_h, bf16* __restrict__ xv_l,
            bf16* __restrict__ xr_h, bf16* __restrict__ xr_l,
            bf16* __restrict__ xg_h, bf16* __restrict__ xg_l)
{
    __shared__ float mps[32][132];
    __shared__ float w2s[32][132];
    const int tid = threadIdx.x;
    const int m0 = blockIdx.y * 128;
    const int n0 = blockIdx.x * 128;
    const int r0 = (tid >> 4) * 8;
    const int c0 = (tid & 15) * 8;
    const float* tms[5] = { tmw, tmk, tmv, tmr, tmg };
    bf16* oh[5] = { xw_h, xk_h, xv_h, xr_h, xg_h };
    bf16* ol[5] = { xw_l, xk_l, xv_l, xr_l, xg_l };

    const int rr  = tid >> 1, cc0 = (tid & 1) * 16;
    const int kr  = tid >> 3, cc1 = (tid & 7) * 16;

    for (int f = 0; f < 5; ++f) {
        {
            const float* src = mixpre + (size_t)(m0 + rr) * 160 + f * 32 + cc0;
            #pragma unroll
            for (int j = 0; j < 16; j += 4) {
                float4 v4 = *(const float4*)(src + j);
                mps[cc0+j+0][rr] = v4.x; mps[cc0+j+1][rr] = v4.y;
                mps[cc0+j+2][rr] = v4.z; mps[cc0+j+3][rr] = v4.w;
            }
            const float* ws = w2 + (size_t)f * 32 * 512 + (size_t)kr * 512 + n0 + cc1;
            #pragma unroll
            for (int j = 0; j < 16; j += 4)
                *(float4*)&w2s[kr][cc1+j] = *(const float4*)(ws + j);
        }
        __syncthreads();

        float acc[8][8];
        #pragma unroll
        for (int i = 0; i < 8; ++i)
            #pragma unroll
            for (int j = 0; j < 8; ++j) acc[i][j] = 0.f;

        #pragma unroll
        for (int k = 0; k < 32; ++k) {
            float a[8], b[8];
            *(float4*)&a[0] = *(const float4*)&mps[k][r0];
            *(float4*)&a[4] = *(const float4*)&mps[k][r0+4];
            *(float4*)&b[0] = *(const float4*)&w2s[k][c0];
            *(float4*)&b[4] = *(const float4*)&w2s[k][c0+4];
            #pragma unroll
            for (int i = 0; i < 8; ++i)
                #pragma unroll
                for (int j = 0; j < 8; ++j)
                    acc[i][j] = fmaf(a[i], b[j], acc[i][j]);
        }

        float tv[8];
        #pragma unroll
        for (int j = 0; j < 8; ++j) tv[j] = __ldg(tms[f] + n0 + c0 + j);

        #pragma unroll
        for (int i = 0; i < 8; ++i) {
            const int row = m0 + r0 + i;
            const size_t base = (size_t)row * CC + n0 + c0;
            float4 x0 = *(const float4*)(x + base);
            float4 x1 = *(const float4*)(x + base + 4);
            float4 d0 = *(const float4*)(xx + base);
            float4 d1 = *(const float4*)(xx + base + 4);
            float o[8];
            o[0] = fmaf(d0.x, tv[0] + acc[i][0], x0.x);
            o[1] = fmaf(d0.y, tv[1] + acc[i][1], x0.y);
            o[2] = fmaf(d0.z, tv[2] + acc[i][2], x0.z);
            o[3] = fmaf(d0.w, tv[3] + acc[i][3], x0.w);
            o[4] = fmaf(d1.x, tv[4] + acc[i][4], x1.x);
            o[5] = fmaf(d1.y, tv[5] + acc[i][5], x1.y);
            o[6] = fmaf(d1.z, tv[6] + acc[i][6], x1.z);
            o[7] = fmaf(d1.w, tv[7] + acc[i][7], x1.w);
            uint4 H, L;
            split2(o[0], o[1], H.x, L.x);
            split2(o[2], o[3], H.y, L.y);
            split2(o[4], o[5], H.z, L.z);
            split2(o[6], o[7], H.w, L.w);
            *(uint4*)(oh[f] + base) = H;
            *(uint4*)(ol[f] + base) = L;
        }
        __syncthreads();
    }
}

// ---------------- WKV6 scan v2 ----------------
// Block = one (b,h), 8 warps. Warp owns 4 value-indices i = warp*4..+3; lane = key j.
// Multi-value butterfly: 9 shfl for 4 reductions.
__device__ __forceinline__ void wkv_step(
    float rc, float kc, float dc, float4 vc, float uj, int lane,
    float& S0, float& S1, float& S2, float& S3, float* yp, int t)
{
    float kv0 = kc * vc.x, kv1 = kc * vc.y, kv2 = kc * vc.z, kv3 = kc * vc.w;
    float z0 = rc * fmaf(uj, kv0, S0);
    float z1 = rc * fmaf(uj, kv1, S1);
    float z2 = rc * fmaf(uj, kv2, S2);
    float z3 = rc * fmaf(uj, kv3, S3);
    S0 = fmaf(dc, S0, kv0);
    S1 = fmaf(dc, S1, kv1);
    S2 = fmaf(dc, S2, kv2);
    S3 = fmaf(dc, S3, kv3);
    // stage 1 (xor 16): lanes<16 keep (i0,i1), lanes>=16 keep (i2,i3)
    float o0 = __shfl_xor_sync(0xffffffffu, z0, 16);
    float o1 = __shfl_xor_sync(0xffffffffu, z1, 16);
    float o2 = __shfl_xor_sync(0xffffffffu, z2, 16);
    float o3 = __shfl_xor_sync(0xffffffffu, z3, 16);
    bool hi16 = lane >= 16;
    float a = hi16 ? (z2 + o2) : (z0 + o0);
    float b = hi16 ? (z3 + o3) : (z1 + o1);
    // stage 2 (xor 8): (lane&8)==0 keeps a-item, else b-item
    float oa = __shfl_xor_sync(0xffffffffu, a, 8);
    float ob = __shfl_xor_sync(0xffffffffu, b, 8);
    float cv = (lane & 8) ? (b + ob) : (a + oa);
    // stages 3-5 within 8-lane groups
    cv += __shfl_xor_sync(0xffffffffu, cv, 4);
    cv += __shfl_xor_sync(0xffffffffu, cv, 2);
    cv += __shfl_xor_sync(0xffffffffu, cv, 1);
    // lane 0->i0, 8->i1, 16->i2, 24->i3
    if ((lane & 7) == 0) yp[(size_t)t * HSZ + (lane >> 3)] = cv;
}

__global__ void __launch_bounds__(256)
wkv_scan(const float* __restrict__ r, const float* __restrict__ k,
         const float* __restrict__ v, const float* __restrict__ d,
         const float* __restrict__ u, float* __restrict__ y)
{
    int bh = blockIdx.x;
    int b = bh >> 4, h = bh & 15;
    int warp = threadIdx.x >> 5, lane = threadIdx.x & 31;
    int i0 = warp * 4;
    size_t base = ((size_t)b * TT) * CC + h * HSZ;

    const float* rp = r + base + lane;
    const float* kp = k + base + lane;
    const float* dp = d + base + lane;
    const float* vp = v + base + i0;
    float* yp = y + ((size_t)bh * TT) * HSZ + i0;

    float uj = u[h * HSZ + lane];
    float S0 = 0.f, S1 = 0.f, S2 = 0.f, S3 = 0.f;

    // prefetch t=0,1 (distance-2 pipeline)
    float rA = rp[0],  kA = kp[0],  dA = dp[0];  float4 vA = *(const float4*)vp;
    float rB = rp[CC], kB = kp[CC], dB = dp[CC]; float4 vB = *(const float4*)(vp + CC);

    for (int t = 0; t < TT; t += 2) {
        float rc = rA, kc = kA, dc = dA; float4 vc = vA;
        if (t + 2 < TT) {
            size_t o = (size_t)(t + 2) * CC;
            rA = rp[o]; kA = kp[o]; dA = dp[o]; vA = *(const float4*)(vp + o);
        }
        wkv_step(rc, kc, dc, vc, uj, lane, S0, S1, S2, S3, yp, t);

        float rc2 = rB, kc2 = kB, dc2 = dB; float4 vc2 = vB;
        if (t + 3 < TT) {
            size_t o = (size_t)(t + 3) * CC;
            rB = rp[o]; kB = kp[o]; dB = dp[o]; vB = *(const float4*)(vp + o);
        }
        wkv_step(rc2, kc2, dc2, vc2, uj, lane, S0, S1, S2, S3, yp, t + 1);
    }
}

// ---------------- per-head groupnorm + gate -> split bf16 ----------------
__global__ void __launch_bounds__(256)
gn_gate(const float* __restrict__ y, const float* __restrict__ g,
        const float* __restrict__ lnw, const float* __restrict__ lnb,
        bf16* __restrict__ out_h, bf16* __restrict__ out_l)
{
    int gwid = blockIdx.x * (blockDim.x >> 5) + (threadIdx.x >> 5);
    int lane = threadIdx.x & 31;
    if (gwid >= BB * HH * TT) return;
    int bh = gwid / TT;
    int t  = gwid % TT;
    int b = bh >> 4, h = bh & 15;

    float yv = y[(size_t)gwid * HSZ + lane];
    float s = yv, s2 = yv * yv;
    #pragma unroll
    for (int off = 16; off >= 1; off >>= 1) {
        s  += __shfl_xor_sync(0xffffffffu, s,  off);
        s2 += __shfl_xor_sync(0xffffffffu, s2, off);
    }
    float mu  = s * (1.f / HSZ);
    float var = s2 * (1.f / HSZ) - mu * mu;
    float rstd = rsqrtf(var + 1e-5f);
    int cidx = h * HSZ + lane;
    float yn = fmaf((yv - mu) * rstd, lnw[cidx], lnb[cidx]);
    size_t oidx = ((size_t)b * TT + t) * CC + cidx;
    float v = yn * g[oidx];
    bf16 hv = __float2bfloat16(v);
    out_h[oidx] = hv;
    out_l[oidx] = __float2bfloat16(v - __bfloat162float(hv));
}

// ---------------- host launcher ----------------
extern "C" void kernel_launch(void* const* d_in, const int* in_sizes, int n_in,
                              void* d_out, int out_size)
{
    const float* x     = (const float*)d_in[0];
    const float* tmxv  = (const float*)d_in[1];
    const float* tmw   = (const float*)d_in[2];
    const float* tmk   = (const float*)d_in[3];
    const float* tmv   = (const float*)d_in[4];
    const float* tmr   = (const float*)d_in[5];
    const float* tmg   = (const float*)d_in[6];
    const float* w1    = (const float*)d_in[7];    // (512,160)
    const float* w2    = (const float*)d_in[8];    // (5,32,512)
    const float* tdec  = (const float*)d_in[9];    // (512)
    const float* tdw1  = (const float*)d_in[10];   // (512,64)
    const float* tdw2  = (const float*)d_in[11];   // (64,512)
    const float* faaaa = (const float*)d_in[12];   // (16,32)
    const float* Wr    = (const float*)d_in[13];
    const float* Wk    = (const float*)d_in[14];
    const float* Wv    = (const float*)d_in[15];
    const float* Wg    = (const float*)d_in[16];
    const float* Wo    = (const float*)d_in[17];
    const float* lnw   = (const float*)d_in[18];
    const float* lnb   = (const float*)d_in[19];
    float* out = (float*)d_out;

    float *p_xx, *p_mix, *p_r, *p_k, *p_v, *p_g, *p_dec, *p_y;
    bf16 *p_xxxh, *p_xxxl, *p_xwh, *p_xwl, *p_xkh, *p_xkl, *p_xvh, *p_xvl,
         *p_xrh, *p_xrl, *p_xgh, *p_xgl, *p_ygh, *p_ygl,
         *p_wth, *p_wtl, *p_wh, *p_wl, *p_w1th, *p_w1tl,
         *p_td1h, *p_td1l, *p_td2h, *p_td2l;
    cudaGetSymbolAddress((void**)&p_xx,   g_xx);
    cudaGetSymbolAddress((void**)&p_mix,  g_mixpre);
    cudaGetSymbolAddress((void**)&p_r,    g_r);
    cudaGetSymbolAddress((void**)&p_k,    g_k);
    cudaGetSymbolAddress((void**)&p_v,    g_v);
    cudaGetSymbolAddress((void**)&p_g,    g_g);
    cudaGetSymbolAddress((void**)&p_dec,  g_dec);
    cudaGetSymbolAddress((void**)&p_y,    g_y);
    cudaGetSymbolAddress((void**)&p_xxxh, g_xxx_h);
    cudaGetSymbolAddress((void**)&p_xxxl, g_xxx_l);
    cudaGetSymbolAddress((void**)&p_xwh,  g_xw_h);
    cudaGetSymbolAddress((void**)&p_xwl,  g_xw_l);
    cudaGetSymbolAddress((void**)&p_xkh,  g_xk_h);
    cudaGetSymbolAddress((void**)&p_xkl,  g_xk_l);
    cudaGetSymbolAddress((void**)&p_xvh,  g_xv_h);
    cudaGetSymbolAddress((void**)&p_xvl,  g_xv_l);
    cudaGetSymbolAddress((void**)&p_xrh,  g_xr_h);
    cudaGetSymbolAddress((void**)&p_xrl,  g_xr_l);
    cudaGetSymbolAddress((void**)&p_xgh,  g_xg_h);
    cudaGetSymbolAddress((void**)&p_xgl,  g_xg_l);
    cudaGetSymbolAddress((void**)&p_ygh,  g_yg_h);
    cudaGetSymbolAddress((void**)&p_ygl,  g_yg_l);
    cudaGetSymbolAddress((void**)&p_wth,  g_wt_h);
    cudaGetSymbolAddress((void**)&p_wtl,  g_wt_l);
    cudaGetSymbolAddress((void**)&p_wh,   g_w_h);
    cudaGetSymbolAddress((void**)&p_wl,   g_w_l);
    cudaGetSymbolAddress((void**)&p_w1th, g_w1t_h);
    cudaGetSymbolAddress((void**)&p_w1tl, g_w1t_l);
    cudaGetSymbolAddress((void**)&p_td1h, g_td1t_h);
    cudaGetSymbolAddress((void**)&p_td1l, g_td1t_l);
    cudaGetSymbolAddress((void**)&p_td2h, g_td2t_h);
    cudaGetSymbolAddress((void**)&p_td2l, g_td2t_l);

    cudaFuncSetAttribute(pgemm<EPI_NONE,false>, cudaFuncAttributeMaxDynamicSharedMemorySize, PSMEM);
    cudaFuncSetAttribute(pgemm<EPI_TANH,false>, cudaFuncAttributeMaxDynamicSharedMemorySize, PSMEM);
    cudaFuncSetAttribute(pgemm<EPI_SILU,false>, cudaFuncAttributeMaxDynamicSharedMemorySize, PSMEM);
    cudaFuncSetAttribute(pgemm<EPI_TANH,true>,  cudaFuncAttributeMaxDynamicSharedMemorySize, PSMEM);
    cudaFuncSetAttribute(pgemm<EPI_DECAY,false>,cudaFuncAttributeMaxDynamicSharedMemorySize, PSMEM);

    const int WN = CC*CC;   // 262144

    // 0) split weights
    split_w<<<(WN + 255)/256, 256>>>(Wr, p_wh + 0*(size_t)WN, p_wl + 0*(size_t)WN, WN);
    split_w<<<(WN + 255)/256, 256>>>(Wk, p_wh + 1*(size_t)WN, p_wl + 1*(size_t)WN, WN);
    split_w<<<(WN + 255)/256, 256>>>(Wv, p_wh + 2*(size_t)WN, p_wl + 2*(size_t)WN, WN);
    split_w<<<(WN + 255)/256, 256>>>(Wg, p_wh + 3*(size_t)WN, p_wl + 3*(size_t)WN, WN);
    split_w<<<(WN + 255)/256, 256>>>(Wo, p_wh + 4*(size_t)WN, p_wl + 4*(size_t)WN, WN);
    split_trans<<<(160*512 + 255)/256, 256>>>(w1,   p_w1th, p_w1tl, 160, 512);
    split_trans<<<(64*512  + 255)/256, 256>>>(tdw1, p_td1h, p_td1l, 64,  512);
    split_trans<<<(512*64  + 255)/256, 256>>>(tdw2, p_td2h, p_td2l, 512, 64);

    // 1) token shift
    prep_kernel<<<(BTC/4 + 255)/256, 256>>>(x, tmxv, p_xx, p_xxxh, p_xxxl);

    const int GY = BT / 128;
    dim3 g512(4, GY), g160(2, GY), g64(1, GY);

    // 2) mixpre = tanh(xxx @ w1)
    pgemm<EPI_TANH,false><<<g160, 256, PSMEM>>>(p_xxxh, p_xxxl, p_w1th, p_w1tl,
                                                p_mix, nullptr, nullptr, 160, 160, 512, nullptr);

    // 3) fused 5-stream mix (all split-bf16 outputs)
    mix5_kernel<<<g512, 256>>>(p_mix, w2, x, p_xx, tmw, tmk, tmv, tmr, tmg,
                               p_xwh, p_xwl, p_xkh, p_xkl, p_xvh, p_xvl,
                               p_xrh, p_xrl, p_xgh, p_xgl);

    // 4) decay: wt = tanh(xw @ tdw1) (split out); dec = exp(-exp(tdec + wt @ tdw2))
    pgemm<EPI_TANH,true><<<g64, 256, PSMEM>>>(p_xwh, p_xwl, p_td1h, p_td1l,
                                              nullptr, p_wth, p_wtl, 64, 64, 512, nullptr);
    pgemm<EPI_DECAY,false><<<g512, 256, PSMEM>>>(p_wth, p_wtl, p_td2h, p_td2l,
                                                 p_dec, nullptr, nullptr, CC, 512, 64, tdec);

    // 5) projections
    pgemm<EPI_NONE,false><<<g512, 256, PSMEM>>>(p_xrh, p_xrl, p_wh + 0*(size_t)WN, p_wl + 0*(size_t)WN,
                                                p_r, nullptr, nullptr, CC, 512, 512, nullptr);
    pgemm<EPI_NONE,false><<<g512, 256, PSMEM>>>(p_xkh, p_xkl, p_wh + 1*(size_t)WN, p_wl + 1*(size_t)WN,
                                                p_k, nullptr, nullptr, CC, 512, 512, nullptr);
    pgemm<EPI_NONE,false><<<g512, 256, PSMEM>>>(p_xvh, p_xvl, p_wh + 2*(size_t)WN, p_wl + 2*(size_t)WN,
                                                p_v, nullptr, nullptr, CC, 512, 512, nullptr);
    pgemm<EPI_SILU,false><<<g512, 256, PSMEM>>>(p_xgh, p_xgl, p_wh + 3*(size_t)WN, p_wl + 3*(size_t)WN,
                                                p_g, nullptr, nullptr, CC, 512, 512, nullptr);

    // 6) WKV6 scan v2 (8 warps per (b,h), 4 i per warp)
    wkv_scan<<<BB*HH, 256>>>(p_r, p_k, p_v, p_dec, faaaa, p_y);

    // 7) groupnorm + gate -> split bf16
    gn_gate<<<(BB*HH*TT)/8, 256>>>(p_y, p_g, lnw, lnb, p_ygh, p_ygl);

    // 8) out = yg @ Wo^T
    pgemm<EPI_NONE,false><<<g512, 256, PSMEM>>>(p_ygh, p_ygl, p_wh + 4*(size_t)WN, p_wl + 4*(size_t)WN,
                                                out, nullptr, nullptr, CC, 512, 512, nullptr);
}

// round 6
// speedup vs baseline: 1.4541x; 1.4541x over previous
#include <cuda_runtime.h>
#include <cuda_bf16.h>
#include <math.h>
#include <stdint.h>

// ---------------- problem constants ----------------
#define BB   8
#define TT   2048
#define CC   512
#define HH   16
#define HSZ  32
#define BT   (BB*TT)            // 16384
#define BTC  8388608            // BT*CC
#define NCH  16                 // scan chunks
#define LCH  128                // chunk length

typedef __nv_bfloat16 bf16;

// ---------------- scratch (static device memory; no allocs) ----------------
__device__ float g_xx [BTC];
__device__ float g_mixpre[BT*160];
__device__ float g_r  [BTC];
__device__ float g_k  [BTC];
__device__ float g_v  [BTC];
__device__ float g_g  [BTC];
__device__ float g_dec[BTC];
__device__ float g_y  [BTC];             // layout (b,h,t,i)
__device__ float g_P  [BB*HH*NCH*HSZ];          // chunk decay products
__device__ float g_T  [BB*HH*NCH*HSZ*HSZ];      // chunk local end states
__device__ float g_Sin[BB*HH*NCH*HSZ*HSZ];      // incoming state per chunk

// split bf16 operand buffers
__device__ bf16 g_xxx_h[BTC]; __device__ bf16 g_xxx_l[BTC];
__device__ bf16 g_xw_h[BTC];  __device__ bf16 g_xw_l[BTC];
__device__ bf16 g_xk_h[BTC];  __device__ bf16 g_xk_l[BTC];
__device__ bf16 g_xv_h[BTC];  __device__ bf16 g_xv_l[BTC];
__device__ bf16 g_xr_h[BTC];  __device__ bf16 g_xr_l[BTC];
__device__ bf16 g_xg_h[BTC];  __device__ bf16 g_xg_l[BTC];
__device__ bf16 g_yg_h[BTC];  __device__ bf16 g_yg_l[BTC];
__device__ bf16 g_wt_h[BT*64]; __device__ bf16 g_wt_l[BT*64];
__device__ bf16 g_w_h [5*CC*CC];   // Wr,Wk,Wv,Wg,Wo split (N,K)
__device__ bf16 g_w_l [5*CC*CC];
__device__ bf16 g_w1t_h[160*CC];   // w1^T  (160,512)
__device__ bf16 g_w1t_l[160*CC];
__device__ bf16 g_td1t_h[64*CC];   // tdw1^T (64,512)
__device__ bf16 g_td1t_l[64*CC];
__device__ bf16 g_td2t_h[CC*64];   // tdw2^T (512,64)
__device__ bf16 g_td2t_l[CC*64];

// ---------------- helpers ----------------
__device__ __forceinline__ uint32_t smem_u32(const void* p) {
    uint32_t a;
    asm("{ .reg .u64 t; cvta.to.shared.u64 t, %1; cvt.u32.u64 %0, t; }" : "=r"(a) : "l"(p));
    return a;
}
__device__ __forceinline__ void ldsm4(uint32_t* r, uint32_t addr) {
    asm volatile("ldmatrix.sync.aligned.m8n8.x4.shared.b16 {%0,%1,%2,%3}, [%4];"
                 : "=r"(r[0]), "=r"(r[1]), "=r"(r[2]), "=r"(r[3]) : "r"(addr));
}
__device__ __forceinline__ void mma16816(float* c, const uint32_t* a, const uint32_t* b) {
    asm volatile("mma.sync.aligned.m16n8k16.row.col.f32.bf16.bf16.f32 "
                 "{%0,%1,%2,%3}, {%4,%5,%6,%7}, {%8,%9}, {%0,%1,%2,%3};"
                 : "+f"(c[0]), "+f"(c[1]), "+f"(c[2]), "+f"(c[3])
                 : "r"(a[0]), "r"(a[1]), "r"(a[2]), "r"(a[3]),
                   "r"(b[0]), "r"(b[1]));
}
__device__ __forceinline__ void cp16(uint32_t dst, const void* src, uint32_t sz) {
    asm volatile("cp.async.cg.shared.global [%0], [%1], 16, %2;"
                 :: "r"(dst), "l"(src), "r"(sz) : "memory");
}
#define CP_COMMIT() asm volatile("cp.async.commit_group;" ::: "memory")
#define CP_WAIT1()  asm volatile("cp.async.wait_group 1;" ::: "memory")
#define CP_WAIT0()  asm volatile("cp.async.wait_group 0;" ::: "memory")

__device__ __forceinline__ void split2(float f0, float f1, uint32_t& hi, uint32_t& lo) {
    __nv_bfloat162 h = __floats2bfloat162_rn(f0, f1);
    float r0 = f0 - __bfloat162float(h.x);
    float r1 = f1 - __bfloat162float(h.y);
    __nv_bfloat162 l = __floats2bfloat162_rn(r0, r1);
    hi = *(uint32_t*)&h;
    lo = *(uint32_t*)&l;
}

// ---------------- epilogues ----------------
enum { EPI_NONE=0, EPI_TANH=1, EPI_SILU=2, EPI_DECAY=4 };

template<int EPI>
__device__ __forceinline__ float apply_epi(float v, int col,
                                           const float* __restrict__ vecn)
{
    if constexpr (EPI == EPI_TANH)  { return tanhf(v); }
    if constexpr (EPI == EPI_SILU)  { return v / (1.f + expf(-v)); }
    if constexpr (EPI == EPI_DECAY) { return expf(-expf(vecn[col] + v)); }
    return v;
}

// ================= pgemm: split-bf16 GEMM, cp.async 3-stage pipeline =================
#define PPAD 40
#define PMAT (128*PPAD*2)          // 10240 B
#define PSTG (4*PMAT)              // 40960 B : Ah,Al,Bh,Bl
#define PSMEM (3*PSTG)             // 122880 B

template<int EPI, bool OSPLIT>
__global__ void __launch_bounds__(256)
pgemm(const bf16* __restrict__ Ah, const bf16* __restrict__ Al,
      const bf16* __restrict__ Bh, const bf16* __restrict__ Bl,
      float* __restrict__ C, bf16* __restrict__ Ch, bf16* __restrict__ Cl,
      int ldc, int N, int K,
      const float* __restrict__ vecn)
{
    extern __shared__ __align__(16) char sm[];
    const int tid  = threadIdx.x;
    const int warp = tid >> 5;
    const int lane = tid & 31;
    const int m0 = blockIdx.y * 128;
    const int n0 = blockIdx.x * 128;
    const int wm = (warp >> 2) * 64;
    const int wn = (warp & 3) * 32;
    const uint32_t sbase = smem_u32(sm);
    const int nch = K >> 5;

    auto issue = [&](int ci) {
        const uint32_t st = sbase + (uint32_t)(ci % 3) * PSTG;
        const int k0 = ci << 5;
        #pragma unroll
        for (int q = 0; q < 8; ++q) {
            const int cid  = q * 256 + tid;
            const int c    = cid & 3;
            const int r    = (cid >> 2) & 127;
            const int mat  = (cid >> 9) & 1;      // 0=hi 1=lo
            const int ab   = cid >> 10;           // 0=A 1=B
            const uint32_t dst = st + (uint32_t)ab * (2*PMAT) + (uint32_t)mat * PMAT
                               + (uint32_t)r * 80 + (uint32_t)c * 16;
            uint32_t sz = 16;
            int row;
            if (ab) {
                row = n0 + r;
                if (row >= N) { sz = 0; row = 0; }
            } else {
                row = m0 + r;
            }
            const bf16* srcb = ab ? (mat ? Bl : Bh) : (mat ? Al : Ah);
            const bf16* src  = srcb + (size_t)row * K + k0 + c * 8;
            cp16(dst, src, sz);
        }
        CP_COMMIT();
    };

    float acc[4][4][4];
    #pragma unroll
    for (int i = 0; i < 4; ++i)
        #pragma unroll
        for (int j = 0; j < 4; ++j)
            #pragma unroll
            for (int q = 0; q < 4; ++q) acc[i][j][q] = 0.f;

    const int a_r  = wm + (lane & 15);
    const int a_c8 = (lane >> 4) << 3;
    const int b_r  = wn + (lane & 7) + ((lane >> 4) << 3);
    const int b_c8 = ((lane >> 3) & 1) << 3;

    issue(0);
    if (nch > 1) issue(1);

    for (int ci = 0; ci < nch; ++ci) {
        if (ci < nch - 1) { CP_WAIT1(); } else { CP_WAIT0(); }
        __syncthreads();
        if (ci + 2 < nch) issue(ci + 2);

        const uint32_t st = sbase + (uint32_t)(ci % 3) * PSTG;
        const uint32_t uA_h = st;
        const uint32_t uA_l = st + PMAT;
        const uint32_t uB_h = st + 2*PMAT;
        const uint32_t uB_l = st + 3*PMAT;

        #pragma unroll
        for (int ks = 0; ks < 2; ++ks) {
            const int k0 = ks * 16;
            uint32_t ah[4][4], al[4][4], bh[2][4], bl[2][4];
            #pragma unroll
            for (int mt = 0; mt < 4; ++mt) {
                uint32_t off = (uint32_t)((a_r + mt*16) * PPAD + k0 + a_c8) * 2;
                ldsm4(ah[mt], uA_h + off);
                ldsm4(al[mt], uA_l + off);
            }
            #pragma unroll
            for (int bp = 0; bp < 2; ++bp) {
                uint32_t off = (uint32_t)((b_r + bp*16) * PPAD + k0 + b_c8) * 2;
                ldsm4(bh[bp], uB_h + off);
                ldsm4(bl[bp], uB_l + off);
            }
            #pragma unroll
            for (int mt = 0; mt < 4; ++mt)
                #pragma unroll
                for (int nt = 0; nt < 4; ++nt) {
                    const uint32_t* fbh = &bh[nt >> 1][(nt & 1) * 2];
                    const uint32_t* fbl = &bl[nt >> 1][(nt & 1) * 2];
                    mma16816(acc[mt][nt], ah[mt], fbh);
                    mma16816(acc[mt][nt], al[mt], fbh);
                    mma16816(acc[mt][nt], ah[mt], fbl);
                }
        }
    }

    // epilogue
    #pragma unroll
    for (int mt = 0; mt < 4; ++mt) {
        const int r0 = m0 + wm + mt*16 + (lane >> 2);
        #pragma unroll
        for (int half = 0; half < 2; ++half) {
            const int row = r0 + half * 8;
            const size_t rb = (size_t)row * ldc;
            #pragma unroll
            for (int nt = 0; nt < 4; ++nt) {
                const int col = n0 + wn + nt*8 + (lane & 3)*2;
                if (col < N) {
                    float v0 = apply_epi<EPI>(acc[mt][nt][half*2+0], col,   vecn);
                    float v1 = apply_epi<EPI>(acc[mt][nt][half*2+1], col+1, vecn);
                    if constexpr (OSPLIT) {
                        uint32_t hh, ll;
                        split2(v0, v1, hh, ll);
                        *(uint32_t*)&Ch[rb + col] = hh;
                        *(uint32_t*)&Cl[rb + col] = ll;
                    } else {
                        *(float2*)&C[rb + col] = make_float2(v0, v1);
                    }
                }
            }
        }
    }
}

// ---------------- weight split kernels ----------------
__global__ void split_w(const float* __restrict__ W, bf16* __restrict__ h,
                        bf16* __restrict__ l, int n)
{
    int i = blockIdx.x * blockDim.x + threadIdx.x;
    if (i >= n) return;
    float v = W[i];
    bf16 hv = __float2bfloat16(v);
    h[i] = hv;
    l[i] = __float2bfloat16(v - __bfloat162float(hv));
}
__global__ void split_trans(const float* __restrict__ src, bf16* __restrict__ h,
                            bf16* __restrict__ l, int N, int K)
{
    int i = blockIdx.x * blockDim.x + threadIdx.x;
    if (i >= N * K) return;
    int n = i / K, k = i % K;
    float v = src[(size_t)k * N + n];
    bf16 hv = __float2bfloat16(v);
    h[i] = hv;
    l[i] = __float2bfloat16(v - __bfloat162float(hv));
}

// ---------------- prep: xx = shift(x)-x ; xxx split bf16 ----------------
__global__ void prep_kernel(const float* __restrict__ x,
                            const float* __restrict__ tmx,
                            float* __restrict__ xx,
                            bf16* __restrict__ xxx_h,
                            bf16* __restrict__ xxx_l)
{
    int i4 = blockIdx.x * blockDim.x + threadIdx.x;
    if (i4 >= BTC/4) return;
    size_t idx = (size_t)i4 * 4;
    int m = (int)(idx / CC);
    int c = (int)(idx % CC);
    int t = m % TT;
    float4 xv = *(const float4*)(x + idx);
    float4 xs;
    if (t == 0) { xs.x = xs.y = xs.z = xs.w = 0.f; }
    else        { xs = *(const float4*)(x + idx - CC); }
    float4 tm = *(const float4*)(tmx + c);
    float4 d, e;
    d.x = xs.x - xv.x; d.y = xs.y - xv.y; d.z = xs.z - xv.z; d.w = xs.w - xv.w;
    e.x = fmaf(d.x, tm.x, xv.x); e.y = fmaf(d.y, tm.y, xv.y);
    e.z = fmaf(d.z, tm.z, xv.z); e.w = fmaf(d.w, tm.w, xv.w);
    *(float4*)(xx + idx) = d;
    uint32_t h0, h1, l0, l1;
    split2(e.x, e.y, h0, l0);
    split2(e.z, e.w, h1, l1);
    *(uint2*)(xxx_h + idx) = make_uint2(h0, h1);
    *(uint2*)(xxx_l + idx) = make_uint2(l0, l1);
}

// ---------------- mix5: fused 5-stream token-mix, all outputs split bf16 ----------------
__global__ void __launch_bounds__(256)
mix5_kernel(const float* __restrict__ mixpre,   // (BT,160)
            const float* __restrict__ w2,       // (5,32,512)
            const float* __restrict__ x,
            const float* __restrict__ xx,
            const float* __restrict__ tmw, const float* __restrict__ tmk,
            const float* __restrict__ tmv, const float* __restrict__ tmr,
            const float* __restrict__ tmg,
            bf16* __restrict__ xw_h, bf16* __restrict__ xw_l,
            bf16* __restrict__ xk_h, bf16* __restrict__ xk_l,
            bf16* __restrict__ xv_h, bf16* __restrict__ xv_l,
            bf16* __restrict__ xr_h, bf16* __restrict__ xr_l,
            bf16* __restrict__ xg_h, bf16* __restrict__ xg_l)
{
    __shared__ float mps[32][132];
    __shared__ float w2s[32][132];
    const int tid = threadIdx.x;
    const int m0 = blockIdx.y * 128;
    const int n0 = blockIdx.x * 128;
    const int r0 = (tid >> 4) * 8;
    const int c0 = (tid & 15) * 8;
    const float* tms[5] = { tmw, tmk, tmv, tmr, tmg };
    bf16* oh[5] = { xw_h, xk_h, xv_h, xr_h, xg_h };
    bf16* ol[5] = { xw_l, xk_l, xv_l, xr_l, xg_l };

    const int rr  = tid >> 1, cc0 = (tid & 1) * 16;
    const int kr  = tid >> 3, cc1 = (tid & 7) * 16;

    for (int f = 0; f < 5; ++f) {
        {
            const float* src = mixpre + (size_t)(m0 + rr) * 160 + f * 32 + cc0;
            #pragma unroll
            for (int j = 0; j < 16; j += 4) {
                float4 v4 = *(const float4*)(src + j);
                mps[cc0+j+0][rr] = v4.x; mps[cc0+j+1][rr] = v4.y;
                mps[cc0+j+2][rr] = v4.z; mps[cc0+j+3][rr] = v4.w;
            }
            const float* ws = w2 + (size_t)f * 32 * 512 + (size_t)kr * 512 + n0 + cc1;
            #pragma unroll
            for (int j = 0; j < 16; j += 4)
                *(float4*)&w2s[kr][cc1+j] = *(const float4*)(ws + j);
        }
        __syncthreads();

        float acc[8][8];
        #pragma unroll
        for (int i = 0; i < 8; ++i)
            #pragma unroll
            for (int j = 0; j < 8; ++j) acc[i][j] = 0.f;

        #pragma unroll
        for (int k = 0; k < 32; ++k) {
            float a[8], b[8];
            *(float4*)&a[0] = *(const float4*)&mps[k][r0];
            *(float4*)&a[4] = *(const float4*)&mps[k][r0+4];
            *(float4*)&b[0] = *(const float4*)&w2s[k][c0];
            *(float4*)&b[4] = *(const float4*)&w2s[k][c0+4];
            #pragma unroll
            for (int i = 0; i < 8; ++i)
                #pragma unroll
                for (int j = 0; j < 8; ++j)
                    acc[i][j] = fmaf(a[i], b[j], acc[i][j]);
        }

        float tv[8];
        #pragma unroll
        for (int j = 0; j < 8; ++j) tv[j] = __ldg(tms[f] + n0 + c0 + j);

        #pragma unroll
        for (int i = 0; i < 8; ++i) {
            const int row = m0 + r0 + i;
            const size_t base = (size_t)row * CC + n0 + c0;
            float4 x0 = *(const float4*)(x + base);
            float4 x1 = *(const float4*)(x + base + 4);
            float4 d0 = *(const float4*)(xx + base);
            float4 d1 = *(const float4*)(xx + base + 4);
            float o[8];
            o[0] = fmaf(d0.x, tv[0] + acc[i][0], x0.x);
            o[1] = fmaf(d0.y, tv[1] + acc[i][1], x0.y);
            o[2] = fmaf(d0.z, tv[2] + acc[i][2], x0.z);
            o[3] = fmaf(d0.w, tv[3] + acc[i][3], x0.w);
            o[4] = fmaf(d1.x, tv[4] + acc[i][4], x1.x);
            o[5] = fmaf(d1.y, tv[5] + acc[i][5], x1.y);
            o[6] = fmaf(d1.z, tv[6] + acc[i][6], x1.z);
            o[7] = fmaf(d1.w, tv[7] + acc[i][7], x1.w);
            uint4 H, L;
            split2(o[0], o[1], H.x, L.x);
            split2(o[2], o[3], H.y, L.y);
            split2(o[4], o[5], H.z, L.z);
            split2(o[6], o[7], H.w, L.w);
            *(uint4*)(oh[f] + base) = H;
            *(uint4*)(ol[f] + base) = L;
        }
        __syncthreads();
    }
}

// ================= WKV6 chunked scan =================
// Recurrence per (b,h,j,i): s_t = d_{j,t} s_{t-1} + k_{j,t} v_{i,t}
// y_{t,i} = sum_j r_{j,t} (s_{t-1} + u_j k_{j,t} v_{i,t})
// Phase A: per (bh, chunk): P[j] = prod d; T[j,i] = end state from 0.
// Phase B: per bh: Sin_{c+1} = P_c (*) Sin_c + T_c  (sequential over 16 chunks).
// Phase C: per (bh, chunk): rerun chunk from Sin, emit y.

__global__ void __launch_bounds__(128)
wkv_phaseA(const float* __restrict__ k, const float* __restrict__ v,
           const float* __restrict__ d,
           float* __restrict__ T, float* __restrict__ P)
{
    const int blk = blockIdx.x;            // bh*NCH + c
    const int bh = blk >> 4, c = blk & 15;
    const int b = bh >> 4, h = bh & 15;
    const int warp = threadIdx.x >> 5, lane = threadIdx.x & 31;
    const int i0 = warp * 8;
    const size_t base = ((size_t)b * TT + (size_t)c * LCH) * CC + h * HSZ;

    const float* kp = k + base + lane;
    const float* dp = d + base + lane;
    const float* vp = v + base + i0;

    float S[8];
    #pragma unroll
    for (int q = 0; q < 8; ++q) S[q] = 0.f;
    float p = 1.f;

    #pragma unroll 2
    for (int t = 0; t < LCH; ++t) {
        const size_t o = (size_t)t * CC;
        float kc = kp[o], dc = dp[o];
        float4 v0 = *(const float4*)(vp + o);
        float4 v1 = *(const float4*)(vp + o + 4);
        p *= dc;
        S[0] = fmaf(dc, S[0], kc * v0.x);
        S[1] = fmaf(dc, S[1], kc * v0.y);
        S[2] = fmaf(dc, S[2], kc * v0.z);
        S[3] = fmaf(dc, S[3], kc * v0.w);
        S[4] = fmaf(dc, S[4], kc * v1.x);
        S[5] = fmaf(dc, S[5], kc * v1.y);
        S[6] = fmaf(dc, S[6], kc * v1.z);
        S[7] = fmaf(dc, S[7], kc * v1.w);
    }
    const size_t tb = ((size_t)blk * 32 + lane) * 32 + i0;
    *(float4*)(T + tb)     = make_float4(S[0], S[1], S[2], S[3]);
    *(float4*)(T + tb + 4) = make_float4(S[4], S[5], S[6], S[7]);
    if (warp == 0) P[blk * 32 + lane] = p;
}

__global__ void __launch_bounds__(256)
wkv_phaseB(const float* __restrict__ P, const float* __restrict__ T,
           float* __restrict__ Sin)
{
    const int bh = blockIdx.x;
    const int e = threadIdx.x * 4;         // element within (j,i) 1024
    const int j = e >> 5;
    float4 s = make_float4(0.f, 0.f, 0.f, 0.f);
    for (int c = 0; c < NCH; ++c) {
        const size_t idx = ((size_t)(bh * NCH + c)) * 1024 + e;
        *(float4*)(Sin + idx) = s;
        const float p = P[(bh * NCH + c) * 32 + j];
        const float4 t4 = *(const float4*)(T + idx);
        s.x = fmaf(p, s.x, t4.x);
        s.y = fmaf(p, s.y, t4.y);
        s.z = fmaf(p, s.z, t4.z);
        s.w = fmaf(p, s.w, t4.w);
    }
}

__global__ void __launch_bounds__(128)
wkv_phaseC(const float* __restrict__ r, const float* __restrict__ k,
           const float* __restrict__ v, const float* __restrict__ d,
           const float* __restrict__ u, const float* __restrict__ Sin,
           float* __restrict__ y)
{
    const int blk = blockIdx.x;
    const int bh = blk >> 4, c = blk & 15;
    const int b = bh >> 4, h = bh & 15;
    const int warp = threadIdx.x >> 5, lane = threadIdx.x & 31;
    const int i0 = warp * 8;
    const size_t base = ((size_t)b * TT + (size_t)c * LCH) * CC + h * HSZ;

    const float* rp = r + base + lane;
    const float* kp = k + base + lane;
    const float* dp = d + base + lane;
    const float* vp = v + base + i0;
    float* yp = y + ((size_t)bh * TT + (size_t)c * LCH) * HSZ + i0;

    const float uj = u[h * HSZ + lane];

    float S[8];
    {
        const size_t sb = ((size_t)blk * 32 + lane) * 32 + i0;
        float4 s0 = *(const float4*)(Sin + sb);
        float4 s1 = *(const float4*)(Sin + sb + 4);
        S[0] = s0.x; S[1] = s0.y; S[2] = s0.z; S[3] = s0.w;
        S[4] = s1.x; S[5] = s1.y; S[6] = s1.z; S[7] = s1.w;
    }

    // output q owned by this lane after the packed butterfly
    const int qsel = (((lane >> 4) & 1) << 2) | (((lane >> 3) & 1) << 1) | ((lane >> 2) & 1);
    const bool wlane = (lane & 3) == 0;

    for (int t = 0; t < LCH; ++t) {
        const size_t o = (size_t)t * CC;
        const float rc = rp[o], kc = kp[o], dc = dp[o];
        const float4 v0 = *(const float4*)(vp + o);
        const float4 v1 = *(const float4*)(vp + o + 4);
        float vv[8] = { v0.x, v0.y, v0.z, v0.w, v1.x, v1.y, v1.z, v1.w };

        float z[8];
        #pragma unroll
        for (int q = 0; q < 8; ++q) {
            const float kv = kc * vv[q];
            z[q] = rc * fmaf(uj, kv, S[q]);
            S[q] = fmaf(dc, S[q], kv);
        }

        // packed butterfly: 8 sums in 16 shfl
        float t0 = z[0] + __shfl_xor_sync(0xffffffffu, z[0], 16);
        float t1 = z[1] + __shfl_xor_sync(0xffffffffu, z[1], 16);
        float t2 = z[2] + __shfl_xor_sync(0xffffffffu, z[2], 16);
        float t3 = z[3] + __shfl_xor_sync(0xffffffffu, z[3], 16);
        float t4 = z[4] + __shfl_xor_sync(0xffffffffu, z[4], 16);
        float t5 = z[5] + __shfl_xor_sync(0xffffffffu, z[5], 16);
        float t6 = z[6] + __shfl_xor_sync(0xffffffffu, z[6], 16);
        float t7 = z[7] + __shfl_xor_sync(0xffffffffu, z[7], 16);
        const bool s4 = lane & 16;
        float a0 = s4 ? t4 : t0;
        float a1 = s4 ? t5 : t1;
        float a2 = s4 ? t6 : t2;
        float a3 = s4 ? t7 : t3;
        float oa0 = __shfl_xor_sync(0xffffffffu, a0, 8);
        float oa1 = __shfl_xor_sync(0xffffffffu, a1, 8);
        float oa2 = __shfl_xor_sync(0xffffffffu, a2, 8);
        float oa3 = __shfl_xor_sync(0xffffffffu, a3, 8);
        const bool s3 = lane & 8;
        float b0 = s3 ? (a2 + oa2) : (a0 + oa0);
        float b1 = s3 ? (a3 + oa3) : (a1 + oa1);
        float ob0 = __shfl_xor_sync(0xffffffffu, b0, 4);
        float ob1 = __shfl_xor_sync(0xffffffffu, b1, 4);
        float cv = (lane & 4) ? (b1 + ob1) : (b0 + ob0);
        cv += __shfl_xor_sync(0xffffffffu, cv, 2);
        cv += __shfl_xor_sync(0xffffffffu, cv, 1);

        if (wlane) yp[(size_t)t * HSZ + qsel] = cv;
    }
}

// ---------------- per-head groupnorm + gate -> split bf16 ----------------
__global__ void __launch_bounds__(256)
gn_gate(const float* __restrict__ y, const float* __restrict__ g,
        const float* __restrict__ lnw, const float* __restrict__ lnb,
        bf16* __restrict__ out_h, bf16* __restrict__ out_l)
{
    int gwid = blockIdx.x * (blockDim.x >> 5) + (threadIdx.x >> 5);
    int lane = threadIdx.x & 31;
    if (gwid >= BB * HH * TT) return;
    int bh = gwid / TT;
    int t  = gwid % TT;
    int b = bh >> 4, h = bh & 15;

    float yv = y[(size_t)gwid * HSZ + lane];
    float s = yv, s2 = yv * yv;
    #pragma unroll
    for (int off = 16; off >= 1; off >>= 1) {
        s  += __shfl_xor_sync(0xffffffffu, s,  off);
        s2 += __shfl_xor_sync(0xffffffffu, s2, off);
    }
    float mu  = s * (1.f / HSZ);
    float var = s2 * (1.f / HSZ) - mu * mu;
    float rstd = rsqrtf(var + 1e-5f);
    int cidx = h * HSZ + lane;
    float yn = fmaf((yv - mu) * rstd, lnw[cidx], lnb[cidx]);
    size_t oidx = ((size_t)b * TT + t) * CC + cidx;
    float v = yn * g[oidx];
    bf16 hv = __float2bfloat16(v);
    out_h[oidx] = hv;
    out_l[oidx] = __float2bfloat16(v - __bfloat162float(hv));
}

// ---------------- host launcher ----------------
extern "C" void kernel_launch(void* const* d_in, const int* in_sizes, int n_in,
                              void* d_out, int out_size)
{
    const float* x     = (const float*)d_in[0];
    const float* tmxv  = (const float*)d_in[1];
    const float* tmw   = (const float*)d_in[2];
    const float* tmk   = (const float*)d_in[3];
    const float* tmv   = (const float*)d_in[4];
    const float* tmr   = (const float*)d_in[5];
    const float* tmg   = (const float*)d_in[6];
    const float* w1    = (const float*)d_in[7];
    const float* w2    = (const float*)d_in[8];
    const float* tdec  = (const float*)d_in[9];
    const float* tdw1  = (const float*)d_in[10];
    const float* tdw2  = (const float*)d_in[11];
    const float* faaaa = (const float*)d_in[12];
    const float* Wr    = (const float*)d_in[13];
    const float* Wk    = (const float*)d_in[14];
    const float* Wv    = (const float*)d_in[15];
    const float* Wg    = (const float*)d_in[16];
    const float* Wo    = (const float*)d_in[17];
    const float* lnw   = (const float*)d_in[18];
    const float* lnb   = (const float*)d_in[19];
    float* out = (float*)d_out;

    float *p_xx, *p_mix, *p_r, *p_k, *p_v, *p_g, *p_dec, *p_y, *p_P, *p_T, *p_Sin;
    bf16 *p_xxxh, *p_xxxl, *p_xwh, *p_xwl, *p_xkh, *p_xkl, *p_xvh, *p_xvl,
         *p_xrh, *p_xrl, *p_xgh, *p_xgl, *p_ygh, *p_ygl,
         *p_wth, *p_wtl, *p_wh, *p_wl, *p_w1th, *p_w1tl,
         *p_td1h, *p_td1l, *p_td2h, *p_td2l;
    cudaGetSymbolAddress((void**)&p_xx,   g_xx);
    cudaGetSymbolAddress((void**)&p_mix,  g_mixpre);
    cudaGetSymbolAddress((void**)&p_r,    g_r);
    cudaGetSymbolAddress((void**)&p_k,    g_k);
    cudaGetSymbolAddress((void**)&p_v,    g_v);
    cudaGetSymbolAddress((void**)&p_g,    g_g);
    cudaGetSymbolAddress((void**)&p_dec,  g_dec);
    cudaGetSymbolAddress((void**)&p_y,    g_y);
    cudaGetSymbolAddress((void**)&p_P,    g_P);
    cudaGetSymbolAddress((void**)&p_T,    g_T);
    cudaGetSymbolAddress((void**)&p_Sin,  g_Sin);
    cudaGetSymbolAddress((void**)&p_xxxh, g_xxx_h);
    cudaGetSymbolAddress((void**)&p_xxxl, g_xxx_l);
    cudaGetSymbolAddress((void**)&p_xwh,  g_xw_h);
    cudaGetSymbolAddress((void**)&p_xwl,  g_xw_l);
    cudaGetSymbolAddress((void**)&p_xkh,  g_xk_h);
    cudaGetSymbolAddress((void**)&p_xkl,  g_xk_l);
    cudaGetSymbolAddress((void**)&p_xvh,  g_xv_h);
    cudaGetSymbolAddress((void**)&p_xvl,  g_xv_l);
    cudaGetSymbolAddress((void**)&p_xrh,  g_xr_h);
    cudaGetSymbolAddress((void**)&p_xrl,  g_xr_l);
    cudaGetSymbolAddress((void**)&p_xgh,  g_xg_h);
    cudaGetSymbolAddress((void**)&p_xgl,  g_xg_l);
    cudaGetSymbolAddress((void**)&p_ygh,  g_yg_h);
    cudaGetSymbolAddress((void**)&p_ygl,  g_yg_l);
    cudaGetSymbolAddress((void**)&p_wth,  g_wt_h);
    cudaGetSymbolAddress((void**)&p_wtl,  g_wt_l);
    cudaGetSymbolAddress((void**)&p_wh,   g_w_h);
    cudaGetSymbolAddress((void**)&p_wl,   g_w_l);
    cudaGetSymbolAddress((void**)&p_w1th, g_w1t_h);
    cudaGetSymbolAddress((void**)&p_w1tl, g_w1t_l);
    cudaGetSymbolAddress((void**)&p_td1h, g_td1t_h);
    cudaGetSymbolAddress((void**)&p_td1l, g_td1t_l);
    cudaGetSymbolAddress((void**)&p_td2h, g_td2t_h);
    cudaGetSymbolAddress((void**)&p_td2l, g_td2t_l);

    cudaFuncSetAttribute(pgemm<EPI_NONE,false>, cudaFuncAttributeMaxDynamicSharedMemorySize, PSMEM);
    cudaFuncSetAttribute(pgemm<EPI_TANH,false>, cudaFuncAttributeMaxDynamicSharedMemorySize, PSMEM);
    cudaFuncSetAttribute(pgemm<EPI_SILU,false>, cudaFuncAttributeMaxDynamicSharedMemorySize, PSMEM);
    cudaFuncSetAttribute(pgemm<EPI_TANH,true>,  cudaFuncAttributeMaxDynamicSharedMemorySize, PSMEM);
    cudaFuncSetAttribute(pgemm<EPI_DECAY,false>,cudaFuncAttributeMaxDynamicSharedMemorySize, PSMEM);

    const int WN = CC*CC;

    // 0) split weights
    split_w<<<(WN + 255)/256, 256>>>(Wr, p_wh + 0*(size_t)WN, p_wl + 0*(size_t)WN, WN);
    split_w<<<(WN + 255)/256, 256>>>(Wk, p_wh + 1*(size_t)WN, p_wl + 1*(size_t)WN, WN);
    split_w<<<(WN + 255)/256, 256>>>(Wv, p_wh + 2*(size_t)WN, p_wl + 2*(size_t)WN, WN);
    split_w<<<(WN + 255)/256, 256>>>(Wg, p_wh + 3*(size_t)WN, p_wl + 3*(size_t)WN, WN);
    split_w<<<(WN + 255)/256, 256>>>(Wo, p_wh + 4*(size_t)WN, p_wl + 4*(size_t)WN, WN);
    split_trans<<<(160*512 + 255)/256, 256>>>(w1,   p_w1th, p_w1tl, 160, 512);
    split_trans<<<(64*512  + 255)/256, 256>>>(tdw1, p_td1h, p_td1l, 64,  512);
    split_trans<<<(512*64  + 255)/256, 256>>>(tdw2, p_td2h, p_td2l, 512, 64);

    // 1) token shift
    prep_kernel<<<(BTC/4 + 255)/256, 256>>>(x, tmxv, p_xx, p_xxxh, p_xxxl);

    const int GY = BT / 128;
    dim3 g512(4, GY), g160(2, GY), g64(1, GY);

    // 2) mixpre = tanh(xxx @ w1)
    pgemm<EPI_TANH,false><<<g160, 256, PSMEM>>>(p_xxxh, p_xxxl, p_w1th, p_w1tl,
                                                p_mix, nullptr, nullptr, 160, 160, 512, nullptr);

    // 3) fused 5-stream mix
    mix5_kernel<<<g512, 256>>>(p_mix, w2, x, p_xx, tmw, tmk, tmv, tmr, tmg,
                               p_xwh, p_xwl, p_xkh, p_xkl, p_xvh, p_xvl,
                               p_xrh, p_xrl, p_xgh, p_xgl);

    // 4) decay chain
    pgemm<EPI_TANH,true><<<g64, 256, PSMEM>>>(p_xwh, p_xwl, p_td1h, p_td1l,
                                              nullptr, p_wth, p_wtl, 64, 64, 512, nullptr);
    pgemm<EPI_DECAY,false><<<g512, 256, PSMEM>>>(p_wth, p_wtl, p_td2h, p_td2l,
                                                 p_dec, nullptr, nullptr, CC, 512, 64, tdec);

    // 5) projections
    pgemm<EPI_NONE,false><<<g512, 256, PSMEM>>>(p_xrh, p_xrl, p_wh + 0*(size_t)WN, p_wl + 0*(size_t)WN,
                                                p_r, nullptr, nullptr, CC, 512, 512, nullptr);
    pgemm<EPI_NONE,false><<<g512, 256, PSMEM>>>(p_xkh, p_xkl, p_wh + 1*(size_t)WN, p_wl + 1*(size_t)WN,
                                                p_k, nullptr, nullptr, CC, 512, 512, nullptr);
    pgemm<EPI_NONE,false><<<g512, 256, PSMEM>>>(p_xvh, p_xvl, p_wh + 2*(size_t)WN, p_wl + 2*(size_t)WN,
                                                p_v, nullptr, nullptr, CC, 512, 512, nullptr);
    pgemm<EPI_SILU,false><<<g512, 256, PSMEM>>>(p_xgh, p_xgl, p_wh + 3*(size_t)WN, p_wl + 3*(size_t)WN,
                                                p_g, nullptr, nullptr, CC, 512, 512, nullptr);

    // 6) WKV6 chunked scan
    wkv_phaseA<<<BB*HH*NCH, 128>>>(p_k, p_v, p_dec, p_T, p_P);
    wkv_phaseB<<<BB*HH, 256>>>(p_P, p_T, p_Sin);
    wkv_phaseC<<<BB*HH*NCH, 128>>>(p_r, p_k, p_v, p_dec, faaaa, p_Sin, p_y);

    // 7) groupnorm + gate -> split bf16
    gn_gate<<<(BB*HH*TT)/8, 256>>>(p_y, p_g, lnw, lnb, p_ygh, p_ygl);

    // 8) out = yg @ Wo^T
    pgemm<EPI_NONE,false><<<g512, 256, PSMEM>>>(p_ygh, p_ygl, p_wh + 4*(size_t)WN, p_wl + 4*(size_t)WN,
                                                out, nullptr, nullptr, CC, 512, 512, nullptr);
}